// round 1
// baseline (speedup 1.0000x reference)
#include <cuda_runtime.h>
#include <math.h>

#define BB   16
#define NN   2048
#define DD   142
#define KNB  10
#define MD   16
#define EH   610          // edge hidden
#define GN   4            // nodes per edge-block
#define RR   (GN*KNB)     // 40 edge rows per block
#define NC   64           // n-chunk width of edge hidden
#define TCP  176          // padded tail width (163 valid: 142 feats_j + 21 dist feats)

// ---------------- scratch (device globals; no allocation) ----------------
__device__ int   g_idx [BB*NN*KNB];
__device__ float g_dist[BB*NN*KNB];
__device__ float g_mi  [BB*NN*MD];
__device__ float g_part[(BB*NN/8)*DD];

__device__ __forceinline__ float silu(float x) {
    return x / (1.f + __expf(-x));
}

// ---------------- kernel 1: KNN (k=10 smallest squared dists, incl self) ----
__global__ void knn_kernel(const float* __restrict__ coors) {
    __shared__ float sd[NN];
    __shared__ float rv[256];
    __shared__ int   ri[256];
    int bi = blockIdx.x;             // b*NN + i
    int b  = bi >> 11;
    int i  = bi & (NN - 1);
    const float* cb = coors + (size_t)b * NN * 3;
    float cx = cb[i*3+0], cy = cb[i*3+1], cz = cb[i*3+2];
    for (int j = threadIdx.x; j < NN; j += 256) {
        float dx = cx - cb[j*3+0];
        float dy = cy - cb[j*3+1];
        float dz = cz - cb[j*3+2];
        sd[j] = dx*dx + dy*dy + dz*dz;
    }
    __syncthreads();
    for (int t = 0; t < KNB; t++) {
        float bv = INFINITY; int bj = -1;
        for (int j = threadIdx.x; j < NN; j += 256) {
            float v = sd[j];
            if (v < bv || (v == bv && j < bj)) { bv = v; bj = j; }
        }
        rv[threadIdx.x] = bv; ri[threadIdx.x] = bj;
        __syncthreads();
        for (int s = 128; s > 0; s >>= 1) {
            if (threadIdx.x < s) {
                float ov = rv[threadIdx.x + s]; int oj = ri[threadIdx.x + s];
                if (ov < rv[threadIdx.x] ||
                    (ov == rv[threadIdx.x] && oj < ri[threadIdx.x])) {
                    rv[threadIdx.x] = ov; ri[threadIdx.x] = oj;
                }
            }
            __syncthreads();
        }
        if (threadIdx.x == 0) {
            g_idx [bi*KNB + t] = ri[0];
            g_dist[bi*KNB + t] = rv[0];
            sd[ri[0]] = INFINITY;
        }
        __syncthreads();
    }
}

// ---------------- kernel 2: fused edge MLP + m_i reduction ----------------
// Edge input col layout: [0:142) feats_i (identical over k -> "base" GEMV per node)
//                        [142:284) feats_j, [284:294) sin, [294:304) cos, [304] d
// Tail array XT holds cols 142..304 remapped to t=0..162 (+ zero pad to 176).
__global__ void __launch_bounds__(128)
edge_kernel(const float* __restrict__ feats,
            const float* __restrict__ We1, const float* __restrict__ be1,
            const float* __restrict__ We2, const float* __restrict__ be2) {
    extern __shared__ float sm[];
    float* fi   = sm;                    // GN*142            = 568
    float* XT   = fi   + GN*142;         // RR*TCP            = 7040
    float* base = XT   + RR*TCP;         // GN*NC             = 256
    float* Wt   = base + GN*NC;          // 16*NC             = 1024
    float* We2t = Wt   + 16*NC;          // NC*MD             = 1024
    float* sH   = We2t + NC*MD;          // RR*NC             = 2560
    float* Ms   = sH   + RR*NC;          // RR*MD             = 640
    int*   sj   = (int*)(Ms + RR*MD);    // RR
    float* sdt  = (float*)(sj + RR);     // RR

    int tid = threadIdx.x;
    int base_gn = blockIdx.x * GN;       // first global node of this block
    int b = base_gn >> 11;

    if (tid < RR) {
        sj [tid] = g_idx [base_gn*KNB + tid];
        sdt[tid] = g_dist[base_gn*KNB + tid];
    }
    for (int v = tid; v < GN*DD; v += 128)
        fi[v] = feats[(size_t)base_gn * DD + v];      // 4 consecutive nodes
    __syncthreads();

    // gather feats_j
    for (int v = tid; v < RR*DD; v += 128) {
        int r = v / DD, c = v - r * DD;
        int j = sj[r];
        XT[r*TCP + c] = feats[((size_t)(b << 11) + j) * DD + c];
    }
    // fourier features + zero pad
    if (tid < RR) {
        float d = sdt[tid];
        float* row = XT + tid * TCP;
        float sc = 1.f;
        #pragma unroll
        for (int f = 0; f < 10; f++) {
            float x = d * sc;
            row[142 + f] = sinf(x);
            row[152 + f] = cosf(x);
            sc *= 0.5f;
        }
        row[162] = d;
        #pragma unroll
        for (int t = 163; t < TCP; t++) row[t] = 0.f;
    }
    __syncthreads();

    int cg = tid & 15;        // col group: 4 cols each
    int rg = tid >> 4;        // row group: 5 rows each (0..7)
    int r0 = rg * 5;
    int nodeOfRows = rg >> 1; // 5-row groups stay inside one node (10 rows/node)
    int mc = tid & 15;        // stage-3 m column
    float macc[5] = {0.f, 0.f, 0.f, 0.f, 0.f};

    for (int chunk = 0; chunk < 10; chunk++) {
        int n0 = chunk * NC;

        // stage 1: per-node base = b_e1 + feats_i @ We1[0:142, n0:n0+64]
        for (int v = tid; v < GN*NC; v += 128) {
            int g = v >> 6, c = v & 63;
            int col = n0 + c;
            float acc = 0.f;
            if (col < EH) {
                const float* wp = We1 + col;
                const float* fp = fi + g * DD;
                float a0 = 0.f, a1 = 0.f;
                #pragma unroll 2
                for (int kk = 0; kk < DD; kk += 2) {
                    a0 += fp[kk]     * wp[kk * EH];
                    a1 += fp[kk + 1] * wp[(kk + 1) * EH];
                }
                acc = be1[col] + a0 + a1;
            }
            base[v] = acc;
        }
        __syncthreads();

        // stage 2: per-edge tail GEMM, 5x4 register tile
        float acc2[5][4];
        {
            int bo = nodeOfRows * NC + cg * 4;
            float b0 = base[bo], b1 = base[bo+1], b2 = base[bo+2], b3 = base[bo+3];
            #pragma unroll
            for (int i = 0; i < 5; i++) {
                acc2[i][0] = b0; acc2[i][1] = b1; acc2[i][2] = b2; acc2[i][3] = b3;
            }
        }
        for (int t0 = 0; t0 < TCP; t0 += 16) {
            for (int v = tid; v < 16*NC; v += 128) {
                int kk = v >> 6, c = v & 63;
                int grow = 142 + t0 + kk;
                int gcol = n0 + c;
                Wt[v] = (grow < 305 && gcol < EH) ? We1[grow * EH + gcol] : 0.f;
            }
            __syncthreads();
            #pragma unroll
            for (int kk = 0; kk < 16; kk++) {
                const float4 wv = *(const float4*)(Wt + kk * NC + cg * 4);
                #pragma unroll
                for (int i = 0; i < 5; i++) {
                    float x = XT[(r0 + i) * TCP + t0 + kk];
                    acc2[i][0] += x * wv.x;
                    acc2[i][1] += x * wv.y;
                    acc2[i][2] += x * wv.z;
                    acc2[i][3] += x * wv.w;
                }
            }
            __syncthreads();
        }

        // silu -> sH ; load We2 tile
        #pragma unroll
        for (int i = 0; i < 5; i++)
            #pragma unroll
            for (int j = 0; j < 4; j++)
                sH[(r0 + i) * NC + cg * 4 + j] = silu(acc2[i][j]);
        for (int v = tid; v < NC*MD; v += 128) {
            int nc = v >> 4, m = v & 15;
            int row = n0 + nc;
            We2t[v] = (row < EH) ? We2[row * MD + m] : 0.f;
        }
        __syncthreads();

        // stage 3: accumulate pre-activation of m_ij
        #pragma unroll 4
        for (int nc = 0; nc < NC; nc++) {
            float w = We2t[nc * MD + mc];
            #pragma unroll
            for (int i = 0; i < 5; i++)
                macc[i] += sH[(r0 + i) * NC + nc] * w;
        }
        __syncthreads();
    }

    // finalize per-edge silu, then reduce K rows per node
    float bb = be2[mc];
    #pragma unroll
    for (int i = 0; i < 5; i++)
        Ms[(r0 + i) * MD + mc] = silu(macc[i] + bb);
    __syncthreads();
    if (tid < GN * MD) {
        int g = tid >> 4, m = tid & 15;
        float s = 0.f;
        #pragma unroll
        for (int k2 = 0; k2 < KNB; k2++) s += Ms[(g * KNB + k2) * MD + m];
        g_mi[(size_t)(base_gn + g) * MD + m] = s;
    }
}

// ---------------- kernel 3: LayerNorm + node MLP + residual + partial sums --
__global__ void __launch_bounds__(256)
node_kernel(const float* __restrict__ feats,
            const float* __restrict__ lng, const float* __restrict__ lnb,
            const float* __restrict__ Wn1, const float* __restrict__ bn1,
            const float* __restrict__ Wn2, const float* __restrict__ bn2) {
    __shared__ float in_s[8 * 160];
    __shared__ float h_s [8 * 288];
    int tid = threadIdx.x;
    int base_gn = blockIdx.x * 8;
    int w = tid >> 5, lane = tid & 31;

    { // warp-per-node layernorm
        int gn = base_gn + w;
        const float* fp = feats + (size_t)gn * DD;
        float s = 0.f, ss = 0.f;
        float vals[5];
        #pragma unroll
        for (int u = 0; u < 5; u++) {
            int c = lane + u * 32;
            float v = (c < DD) ? fp[c] : 0.f;
            vals[u] = v; s += v; ss += v * v;
        }
        #pragma unroll
        for (int o = 16; o; o >>= 1) {
            s  += __shfl_xor_sync(0xffffffffu, s,  o);
            ss += __shfl_xor_sync(0xffffffffu, ss, o);
        }
        float mu  = s * (1.f / DD);
        float var = ss * (1.f / DD) - mu * mu;
        float inv = rsqrtf(var + 1e-5f);
        #pragma unroll
        for (int u = 0; u < 5; u++) {
            int c = lane + u * 32;
            if (c < DD) in_s[w * 160 + c] = (vals[u] - mu) * inv * lng[c] + lnb[c];
        }
        if (lane < MD) in_s[w * 160 + DD + lane] = g_mi[(size_t)gn * MD + lane];
    }
    __syncthreads();

    for (int o = tid; o < 8 * 284; o += 256) {
        int g = o / 284, c = o - g * 284;
        const float* ip = in_s + g * 160;
        const float* wp = Wn1 + c;
        float a0 = 0.f, a1 = 0.f;
        #pragma unroll 2
        for (int kk = 0; kk < 158; kk += 2) {
            a0 += ip[kk]     * wp[kk * 284];
            a1 += ip[kk + 1] * wp[(kk + 1) * 284];
        }
        h_s[g * 288 + c] = silu(bn1[c] + a0 + a1);
    }
    __syncthreads();

    for (int o = tid; o < 8 * DD; o += 256) {
        int g = o / DD, c = o - g * DD;
        const float* hp = h_s + g * 288;
        const float* wp = Wn2 + c;
        float a0 = 0.f, a1 = 0.f;
        #pragma unroll 2
        for (int kk = 0; kk < 284; kk += 2) {
            a0 += hp[kk]     * wp[kk * DD];
            a1 += hp[kk + 1] * wp[(kk + 1) * DD];
        }
        in_s[g * 160 + c] = bn2[c] + a0 + a1 + feats[(size_t)(base_gn + g) * DD + c];
    }
    __syncthreads();

    for (int c = tid; c < DD; c += 256) {
        float s = 0.f;
        #pragma unroll
        for (int g = 0; g < 8; g++) s += in_s[g * 160 + c];
        g_part[(size_t)blockIdx.x * DD + c] = s;
    }
}

// ---------------- kernel 4: deterministic pool + head -----------------------
__global__ void head_kernel(const float* __restrict__ Wout,
                            const float* __restrict__ bout,
                            float* __restrict__ out) {
    __shared__ float red[256];
    int b = blockIdx.x, tid = threadIdx.x;
    const int blocksPerBatch = NN / 8;  // 256
    float v = 0.f;
    if (tid < DD) {
        float s = 0.f;
        const float* pp = g_part + ((size_t)b * blocksPerBatch) * DD + tid;
        for (int blk = 0; blk < blocksPerBatch; blk++) s += pp[(size_t)blk * DD];
        float emb = s * (1.f / (float)NN);
        v = emb * Wout[tid];
    }
    red[tid] = v;
    __syncthreads();
    for (int s2 = 128; s2 > 0; s2 >>= 1) {
        if (tid < s2) red[tid] += red[tid + s2];
        __syncthreads();
    }
    if (tid == 0) out[b] = red[0] + bout[0];
}

// ---------------- launch ----------------------------------------------------
extern "C" void kernel_launch(void* const* d_in, const int* in_sizes, int n_in,
                              void* d_out, int out_size) {
    const float* feats = (const float*)d_in[0];
    const float* coors = (const float*)d_in[1];
    // d_in[2] = mask (all true) ignored; d_in[7..10] = coor MLP (dead) ignored
    const float* We1  = (const float*)d_in[3];
    const float* be1  = (const float*)d_in[4];
    const float* We2  = (const float*)d_in[5];
    const float* be2  = (const float*)d_in[6];
    const float* lng  = (const float*)d_in[11];
    const float* lnb  = (const float*)d_in[12];
    const float* Wn1  = (const float*)d_in[13];
    const float* bn1  = (const float*)d_in[14];
    const float* Wn2  = (const float*)d_in[15];
    const float* bn2  = (const float*)d_in[16];
    const float* Wout = (const float*)d_in[17];
    const float* bout = (const float*)d_in[18];
    float* out = (float*)d_out;

    const int EDGE_SMEM = (GN*142 + RR*TCP + GN*NC + 16*NC + NC*MD + RR*NC +
                           RR*MD + RR + RR) * 4;  // ~52.8 KB

    knn_kernel<<<BB * NN, 256>>>(coors);
    cudaFuncSetAttribute(edge_kernel,
                         cudaFuncAttributeMaxDynamicSharedMemorySize, EDGE_SMEM);
    edge_kernel<<<(BB * NN) / GN, 128, EDGE_SMEM>>>(feats, We1, be1, We2, be2);
    node_kernel<<<(BB * NN) / 8, 256>>>(feats, lng, lnb, Wn1, bn1, Wn2, bn2);
    head_kernel<<<BB, 256>>>(Wout, bout, out);
}

// round 2
// speedup vs baseline: 1.2760x; 1.2760x over previous
#include <cuda_runtime.h>
#include <math.h>

#define BB   16
#define NN   2048
#define DD   142
#define KNB  10
#define MD   16
#define EH   610
#define CPAD 640
#define GN   8
#define RR   (GN*KNB)
#define ETH  320

__device__ int   g_idx [BB*NN*KNB];
__device__ float g_dist[BB*NN*KNB];
__device__ float g_mi  [BB*NN*MD];
__device__ float g_part[(BB*NN/8)*DD];
__device__ float g_base[(size_t)BB*NN*CPAD];
__device__ float g_P   [(size_t)BB*NN*CPAD];

__device__ __forceinline__ float silu(float x) { return x / (1.f + __expf(-x)); }

__device__ __forceinline__ unsigned long long pack2(float x, float y) {
    unsigned long long r;
    asm("mov.b64 %0, {%1, %2};" : "=l"(r) : "f"(x), "f"(y));
    return r;
}
__device__ __forceinline__ void fma2(unsigned long long &d,
                                     unsigned long long a, unsigned long long b) {
    asm("fma.rn.f32x2 %0, %1, %2, %0;" : "+l"(d) : "l"(a), "l"(b));
}
__device__ __forceinline__ void add2(unsigned long long &d, unsigned long long a) {
    asm("add.rn.f32x2 %0, %0, %1;" : "+l"(d) : "l"(a));
}
__device__ __forceinline__ float2 unpack2(unsigned long long v) {
    float2 r;
    asm("mov.b64 {%0, %1}, %2;" : "=f"(r.x), "=f"(r.y) : "l"(v));
    return r;
}

// ---------------- kernel 1: KNN ---------------------------------------------
__global__ void knn_kernel(const float* __restrict__ coors) {
    __shared__ float sd[NN];
    __shared__ float rv[256];
    __shared__ int   ri[256];
    int bi = blockIdx.x;
    int b  = bi >> 11;
    int i  = bi & (NN - 1);
    const float* cb = coors + (size_t)b * NN * 3;
    float cx = cb[i*3+0], cy = cb[i*3+1], cz = cb[i*3+2];
    for (int j = threadIdx.x; j < NN; j += 256) {
        float dx = cx - cb[j*3+0];
        float dy = cy - cb[j*3+1];
        float dz = cz - cb[j*3+2];
        sd[j] = dx*dx + dy*dy + dz*dz;
    }
    __syncthreads();
    for (int t = 0; t < KNB; t++) {
        float bv = INFINITY; int bj = -1;
        for (int j = threadIdx.x; j < NN; j += 256) {
            float v = sd[j];
            if (v < bv || (v == bv && j < bj)) { bv = v; bj = j; }
        }
        rv[threadIdx.x] = bv; ri[threadIdx.x] = bj;
        __syncthreads();
        for (int s = 128; s > 0; s >>= 1) {
            if (threadIdx.x < s) {
                float ov = rv[threadIdx.x + s]; int oj = ri[threadIdx.x + s];
                if (ov < rv[threadIdx.x] ||
                    (ov == rv[threadIdx.x] && oj < ri[threadIdx.x])) {
                    rv[threadIdx.x] = ov; ri[threadIdx.x] = oj;
                }
            }
            __syncthreads();
        }
        if (threadIdx.x == 0) {
            g_idx [bi*KNB + t] = ri[0];
            g_dist[bi*KNB + t] = rv[0];
            sd[ri[0]] = INFINITY;
        }
        __syncthreads();
    }
}

// ---------------- kernel 2: prep GEMM (base & P) -----------------------------
__global__ void __launch_bounds__(256)
prep_kernel(const float* __restrict__ feats,
            const float* __restrict__ We1, const float* __restrict__ be1) {
    __shared__ float As[16][64];
    __shared__ float Bs[16][64];
    int tid = threadIdx.x;
    int tx = tid & 15, ty = tid >> 4;
    int ct = blockIdx.x;
    int nt = blockIdx.y;
    int half = (ct >= 10);
    int colbase = (half ? ct - 10 : ct) * 64;
    size_t n0 = (size_t)nt * 64;

    unsigned long long acc01[4] = {0,0,0,0};
    unsigned long long acc23[4] = {0,0,0,0};

    for (int k0 = 0; k0 < DD; k0 += 16) {
        for (int idx = tid; idx < 1024; idx += 256) {
            int node = idx >> 4, kk = idx & 15;
            int k = k0 + kk;
            As[kk][node] = (k < DD) ? feats[(n0 + node) * DD + k] : 0.f;
        }
        for (int idx = tid; idx < 1024; idx += 256) {
            int kk = idx >> 6, c = idx & 63;
            int k = k0 + kk;
            int cl = colbase + c;
            float wv = 0.f;
            if (k < DD && cl < EH)
                wv = We1[(size_t)((half ? 142 : 0) + k) * EH + cl];
            Bs[kk][c] = wv;
        }
        __syncthreads();
        #pragma unroll
        for (int kk = 0; kk < 16; kk++) {
            unsigned long long b01 = *(const unsigned long long*)&Bs[kk][tx*4];
            unsigned long long b23 = *(const unsigned long long*)&Bs[kk][tx*4+2];
            #pragma unroll
            for (int i = 0; i < 4; i++) {
                float a = As[kk][ty*4+i];
                unsigned long long aa = pack2(a, a);
                fma2(acc01[i], aa, b01);
                fma2(acc23[i], aa, b23);
            }
        }
        __syncthreads();
    }

    float* outp = half ? g_P : g_base;
    #pragma unroll
    for (int i = 0; i < 4; i++) {
        size_t node = n0 + ty*4 + i;
        float2 v01 = unpack2(acc01[i]);
        float2 v23 = unpack2(acc23[i]);
        float vals[4] = {v01.x, v01.y, v23.x, v23.y};
        #pragma unroll
        for (int jj = 0; jj < 4; jj++) {
            int cl = colbase + tx*4 + jj;
            float val = 0.f;
            if (cl < EH) {
                val = vals[jj];
                if (!half) val += be1[cl];
            }
            outp[node * CPAD + cl] = val;
        }
    }
}

// ---------------- kernel 3: per-edge residual + GEMM2 + m_i ------------------
__global__ void __launch_bounds__(ETH)
edge_kernel(const float* __restrict__ We1, const float* __restrict__ We2,
            const float* __restrict__ be2) {
    __shared__ int   sj [RR];
    __shared__ float sdt[RR];
    __shared__ float df_s[RR*24];
    __shared__ float wd_s[21*64];
    __shared__ float we2_s[64*MD];
    __shared__ float base_s[GN*64];
    __shared__ float Ms[RR*MD];

    int tid = threadIdx.x;
    int base_gn = blockIdx.x * GN;
    int b = base_gn >> 11;
    int e = tid >> 2;
    int cg = tid & 3;
    int g = e / 10;

    if (tid < RR) {
        sj [tid] = g_idx [base_gn*KNB + tid];
        sdt[tid] = g_dist[base_gn*KNB + tid];
    }
    __syncthreads();

    for (int v = tid; v < RR*21; v += ETH) {
        int ee = v / 21, t = v - ee*21;
        float d = sdt[ee];
        float f;
        if (t < 10)      f = sinf(ldexpf(d, -t));
        else if (t < 20) f = cosf(ldexpf(d, -(t-10)));
        else             f = d;
        df_s[ee*24 + t] = f;
    }

    size_t jg = (size_t)((b << 11) + sj[e]);
    unsigned long long macc[8] = {0,0,0,0,0,0,0,0};

    for (int chunk = 0; chunk < 10; chunk++) {
        int c0 = chunk * 64;
        for (int v = tid; v < 21*64; v += ETH) {
            int t = v >> 6, c = v & 63;
            int col = c0 + c;
            wd_s[v] = (col < EH) ? We1[(size_t)(284 + t) * EH + col] : 0.f;
        }
        for (int v = tid; v < 64*MD; v += ETH) {
            int c = v >> 4, m = v & 15;
            int col = c0 + c;
            we2_s[v] = (col < EH) ? We2[(size_t)col * MD + m] : 0.f;
        }
        for (int v = tid; v < GN*64; v += ETH) {
            int gg = v >> 6, c = v & 63;
            base_s[v] = g_base[(size_t)(base_gn + gg) * CPAD + c0 + c];
        }
        __syncthreads();

        const float* bp = base_s + g*64 + cg*16;
        const float4* pr = (const float4*)(g_P + jg * CPAD + c0 + cg*16);
        float4 pa = pr[0], pb = pr[1], pc2 = pr[2], pd = pr[3];
        unsigned long long hh[8];
        hh[0] = pack2(bp[0]  + pa.x,  bp[1]  + pa.y);
        hh[1] = pack2(bp[2]  + pa.z,  bp[3]  + pa.w);
        hh[2] = pack2(bp[4]  + pb.x,  bp[5]  + pb.y);
        hh[3] = pack2(bp[6]  + pb.z,  bp[7]  + pb.w);
        hh[4] = pack2(bp[8]  + pc2.x, bp[9]  + pc2.y);
        hh[5] = pack2(bp[10] + pc2.z, bp[11] + pc2.w);
        hh[6] = pack2(bp[12] + pd.x,  bp[13] + pd.y);
        hh[7] = pack2(bp[14] + pd.z,  bp[15] + pd.w);

        const float* dfp = df_s + e*24;
        #pragma unroll
        for (int t = 0; t < 21; t++) {
            unsigned long long dd = pack2(dfp[t], dfp[t]);
            const unsigned long long* wr =
                (const unsigned long long*)(wd_s + t*64 + cg*16);
            #pragma unroll
            for (int cp = 0; cp < 8; cp++) fma2(hh[cp], dd, wr[cp]);
        }
        #pragma unroll
        for (int cp = 0; cp < 8; cp++) {
            float2 v = unpack2(hh[cp]);
            float s0 = silu(v.x), s1 = silu(v.y);
            unsigned long long x0 = pack2(s0, s0), x1 = pack2(s1, s1);
            const unsigned long long* wa =
                (const unsigned long long*)(we2_s + (cg*16 + 2*cp) * MD);
            const unsigned long long* wb = wa + 8;
            #pragma unroll
            for (int mp = 0; mp < 8; mp++) {
                fma2(macc[mp], x0, wa[mp]);
                fma2(macc[mp], x1, wb[mp]);
            }
        }
        __syncthreads();
    }

    #pragma unroll
    for (int mp = 0; mp < 8; mp++) {
        unsigned long long o1 = __shfl_xor_sync(0xffffffffu, macc[mp], 1);
        add2(macc[mp], o1);
        unsigned long long o2 = __shfl_xor_sync(0xffffffffu, macc[mp], 2);
        add2(macc[mp], o2);
    }
    if (cg == 0) {
        // m_ij = silu(pre + be2)  (per edge, before K-sum)
        #pragma unroll
        for (int mp = 0; mp < 8; mp++) {
            float2 v = unpack2(macc[mp]);
            Ms[e*MD + 2*mp]     = silu(v.x + be2[2*mp]);
            Ms[e*MD + 2*mp + 1] = silu(v.y + be2[2*mp + 1]);
        }
    }
    __syncthreads();
    if (tid < GN*MD) {
        int gg = tid >> 4, m = tid & 15;
        float s = 0.f;
        #pragma unroll
        for (int k2 = 0; k2 < KNB; k2++) s += Ms[(gg*KNB + k2)*MD + m];
        g_mi[(size_t)(base_gn + gg)*MD + m] = s;
    }
}

// ---------------- kernel 4: LayerNorm + node MLP + residual ------------------
__global__ void __launch_bounds__(256)
node_kernel(const float* __restrict__ feats,
            const float* __restrict__ lng, const float* __restrict__ lnb,
            const float* __restrict__ Wn1, const float* __restrict__ bn1,
            const float* __restrict__ Wn2, const float* __restrict__ bn2) {
    __shared__ float in_s[8 * 160];
    __shared__ float h_s [8 * 288];
    int tid = threadIdx.x;
    int base_gn = blockIdx.x * 8;
    int w = tid >> 5, lane = tid & 31;

    {
        int gn = base_gn + w;
        const float* fp = feats + (size_t)gn * DD;
        float s = 0.f, ss = 0.f;
        float vals[5];
        #pragma unroll
        for (int u = 0; u < 5; u++) {
            int c = lane + u * 32;
            float v = (c < DD) ? fp[c] : 0.f;
            vals[u] = v; s += v; ss += v * v;
        }
        #pragma unroll
        for (int o = 16; o; o >>= 1) {
            s  += __shfl_xor_sync(0xffffffffu, s,  o);
            ss += __shfl_xor_sync(0xffffffffu, ss, o);
        }
        float mu  = s * (1.f / DD);
        float var = ss * (1.f / DD) - mu * mu;
        float inv = rsqrtf(var + 1e-5f);
        #pragma unroll
        for (int u = 0; u < 5; u++) {
            int c = lane + u * 32;
            if (c < DD) in_s[w * 160 + c] = (vals[u] - mu) * inv * lng[c] + lnb[c];
        }
        if (lane < MD) in_s[w * 160 + DD + lane] = g_mi[(size_t)gn * MD + lane];
    }
    __syncthreads();

    for (int o = tid; o < 8 * 142; o += 256) {
        int gg = o / 142, cp = o - gg * 142;
        int c = 2 * cp;
        const float* ip = in_s + gg * 160;
        unsigned long long acc = pack2(bn1[c], bn1[c+1]);
        #pragma unroll 2
        for (int kk = 0; kk < 158; kk++) {
            unsigned long long xx = pack2(ip[kk], ip[kk]);
            unsigned long long ww = *(const unsigned long long*)(Wn1 + (size_t)kk * 284 + c);
            fma2(acc, xx, ww);
        }
        float2 v = unpack2(acc);
        h_s[gg * 288 + c]     = silu(v.x);
        h_s[gg * 288 + c + 1] = silu(v.y);
    }
    __syncthreads();

    for (int o = tid; o < 8 * 71; o += 256) {
        int gg = o / 71, cp = o - gg * 71;
        int c = 2 * cp;
        const float* hp = h_s + gg * 288;
        unsigned long long acc = pack2(bn2[c], bn2[c+1]);
        #pragma unroll 2
        for (int kk = 0; kk < 284; kk++) {
            unsigned long long xx = pack2(hp[kk], hp[kk]);
            unsigned long long ww = *(const unsigned long long*)(Wn2 + (size_t)kk * DD + c);
            fma2(acc, xx, ww);
        }
        float2 v = unpack2(acc);
        size_t gn = base_gn + gg;
        in_s[gg * 160 + c]     = v.x + feats[gn * DD + c];
        in_s[gg * 160 + c + 1] = v.y + feats[gn * DD + c + 1];
    }
    __syncthreads();

    for (int c = tid; c < DD; c += 256) {
        float s = 0.f;
        #pragma unroll
        for (int gg = 0; gg < 8; gg++) s += in_s[gg * 160 + c];
        g_part[(size_t)blockIdx.x * DD + c] = s;
    }
}

// ---------------- kernel 5: pool + head --------------------------------------
__global__ void head_kernel(const float* __restrict__ Wout,
                            const float* __restrict__ bout,
                            float* __restrict__ out) {
    __shared__ float red[256];
    int b = blockIdx.x, tid = threadIdx.x;
    const int blocksPerBatch = NN / 8;
    float v = 0.f;
    if (tid < DD) {
        float s = 0.f;
        const float* pp = g_part + ((size_t)b * blocksPerBatch) * DD + tid;
        for (int blk = 0; blk < blocksPerBatch; blk++) s += pp[(size_t)blk * DD];
        float emb = s * (1.f / (float)NN);
        v = emb * Wout[tid];
    }
    red[tid] = v;
    __syncthreads();
    for (int s2 = 128; s2 > 0; s2 >>= 1) {
        if (tid < s2) red[tid] += red[tid + s2];
        __syncthreads();
    }
    if (tid == 0) out[b] = red[0] + bout[0];
}

// ---------------- launch ----------------------------------------------------
extern "C" void kernel_launch(void* const* d_in, const int* in_sizes, int n_in,
                              void* d_out, int out_size) {
    const float* feats = (const float*)d_in[0];
    const float* coors = (const float*)d_in[1];
    const float* We1  = (const float*)d_in[3];
    const float* be1  = (const float*)d_in[4];
    const float* We2  = (const float*)d_in[5];
    const float* be2  = (const float*)d_in[6];
    const float* lng  = (const float*)d_in[11];
    const float* lnb  = (const float*)d_in[12];
    const float* Wn1  = (const float*)d_in[13];
    const float* bn1  = (const float*)d_in[14];
    const float* Wn2  = (const float*)d_in[15];
    const float* bn2  = (const float*)d_in[16];
    const float* Wout = (const float*)d_in[17];
    const float* bout = (const float*)d_in[18];
    float* out = (float*)d_out;

    knn_kernel<<<BB * NN, 256>>>(coors);
    dim3 pg(20, 512);
    prep_kernel<<<pg, 256>>>(feats, We1, be1);
    edge_kernel<<<(BB * NN) / GN, ETH>>>(We1, We2, be2);
    node_kernel<<<(BB * NN) / 8, 256>>>(feats, lng, lnb, Wn1, bn1, Wn2, bn2);
    head_kernel<<<BB, 256>>>(Wout, bout, out);
}

// round 3
// speedup vs baseline: 2.0107x; 1.5758x over previous
#include <cuda_runtime.h>
#include <math.h>

#define BB   16
#define NN   2048
#define DD   142
#define KNB  10
#define MD   16
#define EH   610
#define CPAD 640
#define GN   8
#define RR   (GN*KNB)
#define ETH  160

__device__ int   g_idx [BB*NN*KNB];
__device__ float g_dist[BB*NN*KNB];
__device__ float g_mi  [BB*NN*MD];
__device__ float g_part[(BB*NN/8)*DD];
__device__ float g_base[(size_t)BB*NN*CPAD];
__device__ float g_P   [(size_t)BB*NN*CPAD];

__device__ __forceinline__ float silu(float x) { return x / (1.f + __expf(-x)); }

__device__ __forceinline__ unsigned long long pack2(float x, float y) {
    unsigned long long r;
    asm("mov.b64 %0, {%1, %2};" : "=l"(r) : "f"(x), "f"(y));
    return r;
}
__device__ __forceinline__ void fma2(unsigned long long &d,
                                     unsigned long long a, unsigned long long b) {
    asm("fma.rn.f32x2 %0, %1, %2, %0;" : "+l"(d) : "l"(a), "l"(b));
}
__device__ __forceinline__ void add2(unsigned long long &d, unsigned long long a) {
    asm("add.rn.f32x2 %0, %0, %1;" : "+l"(d) : "l"(a));
}
__device__ __forceinline__ float2 unpack2(unsigned long long v) {
    float2 r;
    asm("mov.b64 {%0, %1}, %2;" : "=f"(r.x), "=f"(r.y) : "l"(v));
    return r;
}

// ---------------- kernel 1: KNN (regs + warp shuffle) -----------------------
__global__ void __launch_bounds__(256) knn_kernel(const float* __restrict__ coors) {
    __shared__ float swv[8];
    __shared__ int   swi[8];
    __shared__ int   s_win;
    int bi = blockIdx.x;
    int b  = bi >> 11;
    int i  = bi & (NN - 1);
    int tid = threadIdx.x, lane = tid & 31, warp = tid >> 5;
    const float* cb = coors + (size_t)b * NN * 3;
    float cx = cb[i*3+0], cy = cb[i*3+1], cz = cb[i*3+2];
    float vals[8];
    #pragma unroll
    for (int u = 0; u < 8; u++) {
        int j = u * 256 + tid;
        float dx = cx - cb[j*3+0];
        float dy = cy - cb[j*3+1];
        float dz = cz - cb[j*3+2];
        vals[u] = dx*dx + dy*dy + dz*dz;
    }
    for (int t = 0; t < KNB; t++) {
        float bv = vals[0]; int bj = tid;
        #pragma unroll
        for (int u = 1; u < 8; u++) {
            float v = vals[u]; int j = u * 256 + tid;
            if (v < bv) { bv = v; bj = j; }
        }
        #pragma unroll
        for (int off = 16; off; off >>= 1) {
            float ov = __shfl_down_sync(0xffffffffu, bv, off);
            int   oj = __shfl_down_sync(0xffffffffu, bj, off);
            if (ov < bv || (ov == bv && oj < bj)) { bv = ov; bj = oj; }
        }
        if (lane == 0) { swv[warp] = bv; swi[warp] = bj; }
        __syncthreads();
        if (tid == 0) {
            float fv = swv[0]; int fj = swi[0];
            #pragma unroll
            for (int w = 1; w < 8; w++) {
                float ov = swv[w]; int oj = swi[w];
                if (ov < fv || (ov == fv && oj < fj)) { fv = ov; fj = oj; }
            }
            g_idx [bi*KNB + t] = fj;
            g_dist[bi*KNB + t] = fv;
            s_win = fj;
        }
        __syncthreads();
        int wj = s_win;
        if ((wj & 255) == tid) vals[wj >> 8] = INFINITY;
    }
}

// ---------------- kernel 2: prep GEMM (base & P), 128x64 tiles --------------
__global__ void __launch_bounds__(256)
prep_kernel(const float* __restrict__ feats,
            const float* __restrict__ We1, const float* __restrict__ be1) {
    __shared__ float As2[128][18];
    __shared__ float Bs[16][64];
    int tid = threadIdx.x;
    int tx = tid & 7, ty = tid >> 3;       // tx: 8 cols, ty: 4 rows each
    int ct = blockIdx.x;
    int half = (ct >= 10);
    int colbase = (half ? ct - 10 : ct) * 64;
    size_t n0 = (size_t)blockIdx.y * 128;
    int wrow0 = half ? 142 : 0;

    unsigned long long acc[4][4];
    #pragma unroll
    for (int i = 0; i < 4; i++)
        #pragma unroll
        for (int j = 0; j < 4; j++) acc[i][j] = 0ull;

    for (int k0 = 0; k0 < DD; k0 += 16) {
        #pragma unroll
        for (int p = 0; p < 4; p++) {
            int idx = tid + p * 256;
            int node = idx >> 3, kp = (idx & 7) * 2;
            int k = k0 + kp;
            float2 v = make_float2(0.f, 0.f);
            if (k < DD)
                v = *(const float2*)(feats + (n0 + node) * DD + k);
            As2[node][kp] = v.x; As2[node][kp+1] = v.y;
        }
        #pragma unroll
        for (int p = 0; p < 2; p++) {
            int idx = tid + p * 256;
            int kk = idx >> 5, cpos = (idx & 31) * 2;
            int k = k0 + kk;
            float2 v = make_float2(0.f, 0.f);
            if (k < DD && colbase + cpos + 1 < EH)
                v = *(const float2*)(We1 + (size_t)(wrow0 + k) * EH + colbase + cpos);
            else if (k < DD && colbase + cpos < EH)
                v.x = We1[(size_t)(wrow0 + k) * EH + colbase + cpos];
            Bs[kk][cpos] = v.x; Bs[kk][cpos+1] = v.y;
        }
        __syncthreads();
        #pragma unroll
        for (int kk = 0; kk < 16; kk++) {
            ulonglong2 w01 = *(const ulonglong2*)&Bs[kk][tx*8];
            ulonglong2 w23 = *(const ulonglong2*)&Bs[kk][tx*8+4];
            #pragma unroll
            for (int i = 0; i < 4; i++) {
                float a = As2[ty*4 + i][kk];
                unsigned long long pa = pack2(a, a);
                fma2(acc[i][0], pa, w01.x);
                fma2(acc[i][1], pa, w01.y);
                fma2(acc[i][2], pa, w23.x);
                fma2(acc[i][3], pa, w23.y);
            }
        }
        __syncthreads();
    }

    float* outp = half ? g_P : g_base;
    #pragma unroll
    for (int i = 0; i < 4; i++) {
        size_t node = n0 + ty*4 + i;
        float ov[8];
        #pragma unroll
        for (int j = 0; j < 4; j++) {
            float2 v = unpack2(acc[i][j]);
            ov[2*j] = v.x; ov[2*j+1] = v.y;
        }
        #pragma unroll
        for (int j = 0; j < 8; j++) {
            int cl = colbase + tx*8 + j;
            float val = 0.f;
            if (cl < EH) {
                val = ov[j];
                if (!half) val += be1[cl];
            }
            ov[j] = val;
        }
        float* op = outp + node * CPAD + colbase + tx*8;
        *(float4*)op       = make_float4(ov[0], ov[1], ov[2], ov[3]);
        *(float4*)(op + 4) = make_float4(ov[4], ov[5], ov[6], ov[7]);
    }
}

// ---------------- kernel 3: per-edge residual + GEMM2 + m_i (2 edges/thread)-
__global__ void __launch_bounds__(ETH)
edge_kernel(const float* __restrict__ We1, const float* __restrict__ We2,
            const float* __restrict__ be2) {
    __shared__ int   sj [RR];
    __shared__ float sdt[RR];
    __shared__ float df_s[RR*24];
    __shared__ float wd_s[21*64];
    __shared__ float we2_s[64*MD];
    __shared__ float base_s[GN*64];
    __shared__ float Ms[RR*MD];

    int tid = threadIdx.x;
    int base_gn = blockIdx.x * GN;
    int b = base_gn >> 11;
    int cg = tid & 3;            // col quarter (16 cols)
    int pp = tid >> 2;           // edge pair 0..39
    int g  = pp / 5;
    int pl = pp % 5;
    int e0 = g * 10 + 2 * pl;
    int e1 = e0 + 1;

    if (tid < RR) {
        sj [tid] = g_idx [base_gn*KNB + tid];
        sdt[tid] = g_dist[base_gn*KNB + tid];
    }
    __syncthreads();

    for (int v = tid; v < RR*21; v += ETH) {
        int ee = v / 21, t = v - ee*21;
        float d = sdt[ee];
        float f;
        if (t < 10)      f = sinf(ldexpf(d, -t));
        else if (t < 20) f = cosf(ldexpf(d, -(t-10)));
        else             f = d;
        df_s[ee*24 + t] = f;
    }

    size_t jg0 = (size_t)((b << 11) + sj[e0]);
    size_t jg1 = (size_t)((b << 11) + sj[e1]);
    unsigned long long macc0[8] = {0,0,0,0,0,0,0,0};
    unsigned long long macc1[8] = {0,0,0,0,0,0,0,0};

    for (int chunk = 0; chunk < 10; chunk++) {
        int c0 = chunk * 64;
        // stage weights + base
        for (int v = tid; v < 21*32; v += ETH) {       // float2 over 21x64
            int t = v / 32, c = (v - t*32) * 2;
            int col = c0 + c;
            float2 w = make_float2(0.f, 0.f);
            if (col + 1 < EH)
                w = *(const float2*)(We1 + (size_t)(284 + t) * EH + col);
            else if (col < EH)
                w.x = We1[(size_t)(284 + t) * EH + col];
            wd_s[t*64 + c] = w.x; wd_s[t*64 + c + 1] = w.y;
        }
        for (int v = tid; v < 64*MD/4; v += ETH) {     // float4 over contiguous
            int off = v * 4;
            int col = c0 + (off >> 4);
            float4 w = make_float4(0.f,0.f,0.f,0.f);
            if (col < EH)
                w = *(const float4*)(We2 + (size_t)c0 * MD + off);
            *(float4*)(we2_s + off) = w;
        }
        for (int v = tid; v < GN*64/4; v += ETH) {
            int off = v * 4;
            int gg = off >> 6;
            *(float4*)(base_s + off) =
                *(const float4*)(g_base + (size_t)(base_gn + gg) * CPAD + c0 + (off & 63));
        }
        __syncthreads();

        const float* bp = base_s + g*64 + cg*16;
        const float4* pr0 = (const float4*)(g_P + jg0 * CPAD + c0 + cg*16);
        const float4* pr1 = (const float4*)(g_P + jg1 * CPAD + c0 + cg*16);
        unsigned long long h0[8], h1[8];
        #pragma unroll
        for (int q = 0; q < 4; q++) {
            float4 p0 = pr0[q], p1 = pr1[q];
            float b0 = bp[4*q], b1 = bp[4*q+1], b2 = bp[4*q+2], b3 = bp[4*q+3];
            h0[2*q]   = pack2(b0 + p0.x, b1 + p0.y);
            h0[2*q+1] = pack2(b2 + p0.z, b3 + p0.w);
            h1[2*q]   = pack2(b0 + p1.x, b1 + p1.y);
            h1[2*q+1] = pack2(b2 + p1.z, b3 + p1.w);
        }

        const float* dfp0 = df_s + e0*24;
        const float* dfp1 = df_s + e1*24;
        #pragma unroll
        for (int t = 0; t < 21; t++) {
            const unsigned long long* wr =
                (const unsigned long long*)(wd_s + t*64 + cg*16);
            unsigned long long d0 = pack2(dfp0[t], dfp0[t]);
            unsigned long long d1 = pack2(dfp1[t], dfp1[t]);
            #pragma unroll
            for (int q = 0; q < 8; q++) {
                unsigned long long w = wr[q];
                fma2(h0[q], d0, w);
                fma2(h1[q], d1, w);
            }
        }
        #pragma unroll
        for (int cp = 0; cp < 8; cp++) {
            const unsigned long long* wa =
                (const unsigned long long*)(we2_s + (cg*16 + 2*cp) * MD);
            const unsigned long long* wb = wa + 8;
            float2 v0 = unpack2(h0[cp]);
            float2 v1 = unpack2(h1[cp]);
            unsigned long long x00 = pack2(silu(v0.x), silu(v0.x));
            unsigned long long x01 = pack2(silu(v0.y), silu(v0.y));
            unsigned long long x10 = pack2(silu(v1.x), silu(v1.x));
            unsigned long long x11 = pack2(silu(v1.y), silu(v1.y));
            #pragma unroll
            for (int mp = 0; mp < 8; mp++) {
                unsigned long long wam = wa[mp], wbm = wb[mp];
                fma2(macc0[mp], x00, wam);
                fma2(macc0[mp], x01, wbm);
                fma2(macc1[mp], x10, wam);
                fma2(macc1[mp], x11, wbm);
            }
        }
        __syncthreads();
    }

    #pragma unroll
    for (int mp = 0; mp < 8; mp++) {
        add2(macc0[mp], __shfl_xor_sync(0xffffffffu, macc0[mp], 1));
        add2(macc0[mp], __shfl_xor_sync(0xffffffffu, macc0[mp], 2));
        add2(macc1[mp], __shfl_xor_sync(0xffffffffu, macc1[mp], 1));
        add2(macc1[mp], __shfl_xor_sync(0xffffffffu, macc1[mp], 2));
    }
    if (cg == 0) {
        #pragma unroll
        for (int mp = 0; mp < 8; mp++) {
            float2 v0 = unpack2(macc0[mp]);
            float2 v1 = unpack2(macc1[mp]);
            float bb0 = be2[2*mp], bb1 = be2[2*mp+1];
            Ms[e0*MD + 2*mp]     = silu(v0.x + bb0);
            Ms[e0*MD + 2*mp + 1] = silu(v0.y + bb1);
            Ms[e1*MD + 2*mp]     = silu(v1.x + bb0);
            Ms[e1*MD + 2*mp + 1] = silu(v1.y + bb1);
        }
    }
    __syncthreads();
    if (tid < GN*MD) {
        int gg = tid >> 4, m = tid & 15;
        float s = 0.f;
        #pragma unroll
        for (int k2 = 0; k2 < KNB; k2++) s += Ms[(gg*KNB + k2)*MD + m];
        g_mi[(size_t)(base_gn + gg)*MD + m] = s;
    }
}

// ---------------- kernel 4: LayerNorm + node MLP (2-node reg tiles) ---------
__global__ void __launch_bounds__(256)
node_kernel(const float* __restrict__ feats,
            const float* __restrict__ lng, const float* __restrict__ lnb,
            const float* __restrict__ Wn1, const float* __restrict__ bn1,
            const float* __restrict__ Wn2, const float* __restrict__ bn2) {
    __shared__ float in_s[8 * 160];
    __shared__ float h_s [8 * 288];
    int tid = threadIdx.x;
    int base_gn = blockIdx.x * 8;
    int w = tid >> 5, lane = tid & 31;

    {
        int gn = base_gn + w;
        const float* fp = feats + (size_t)gn * DD;
        float s = 0.f, ss = 0.f;
        float vals[5];
        #pragma unroll
        for (int u = 0; u < 5; u++) {
            int c = lane + u * 32;
            float v = (c < DD) ? fp[c] : 0.f;
            vals[u] = v; s += v; ss += v * v;
        }
        #pragma unroll
        for (int o = 16; o; o >>= 1) {
            s  += __shfl_xor_sync(0xffffffffu, s,  o);
            ss += __shfl_xor_sync(0xffffffffu, ss, o);
        }
        float mu  = s * (1.f / DD);
        float var = ss * (1.f / DD) - mu * mu;
        float inv = rsqrtf(var + 1e-5f);
        #pragma unroll
        for (int u = 0; u < 5; u++) {
            int c = lane + u * 32;
            if (c < DD) in_s[w * 160 + c] = (vals[u] - mu) * inv * lng[c] + lnb[c];
        }
        if (lane < MD) in_s[w * 160 + DD + lane] = g_mi[(size_t)gn * MD + lane];
    }
    __syncthreads();

    // stage 1: 2 nodes x 4 cols per item; 4 node-pairs * 71 col-groups = 284
    for (int o = tid; o < 284; o += 256) {
        int ng  = o & 3;
        int cgi = o >> 2;
        int c = cgi * 4;
        const float* ip0 = in_s + (2*ng)     * 160;
        const float* ip1 = in_s + (2*ng + 1) * 160;
        unsigned long long a00 = pack2(bn1[c],   bn1[c+1]);
        unsigned long long a01 = pack2(bn1[c+2], bn1[c+3]);
        unsigned long long a10 = a00, a11 = a01;
        #pragma unroll 2
        for (int kk = 0; kk < 158; kk++) {
            ulonglong2 ww = *(const ulonglong2*)(Wn1 + (size_t)kk * 284 + c);
            unsigned long long x0 = pack2(ip0[kk], ip0[kk]);
            unsigned long long x1 = pack2(ip1[kk], ip1[kk]);
            fma2(a00, x0, ww.x); fma2(a01, x0, ww.y);
            fma2(a10, x1, ww.x); fma2(a11, x1, ww.y);
        }
        float2 v;
        float* hp0 = h_s + (2*ng) * 288 + c;
        float* hp1 = hp0 + 288;
        v = unpack2(a00); hp0[0] = silu(v.x); hp0[1] = silu(v.y);
        v = unpack2(a01); hp0[2] = silu(v.x); hp0[3] = silu(v.y);
        v = unpack2(a10); hp1[0] = silu(v.x); hp1[1] = silu(v.y);
        v = unpack2(a11); hp1[2] = silu(v.x); hp1[3] = silu(v.y);
    }
    __syncthreads();

    // stage 2: 2 nodes x 2 cols per item; 4 node-pairs * 71 col-groups = 284
    for (int o = tid; o < 284; o += 256) {
        int ng  = o & 3;
        int cgi = o >> 2;
        int c = cgi * 2;
        const float* hp0 = h_s + (2*ng)     * 288;
        const float* hp1 = h_s + (2*ng + 1) * 288;
        unsigned long long a0 = pack2(bn2[c], bn2[c+1]);
        unsigned long long a1 = a0;
        #pragma unroll 2
        for (int kk = 0; kk < 284; kk++) {
            unsigned long long ww = *(const unsigned long long*)(Wn2 + (size_t)kk * DD + c);
            unsigned long long x0 = pack2(hp0[kk], hp0[kk]);
            unsigned long long x1 = pack2(hp1[kk], hp1[kk]);
            fma2(a0, x0, ww);
            fma2(a1, x1, ww);
        }
        size_t gn0 = base_gn + 2*ng;
        float2 v0 = unpack2(a0);
        float2 v1 = unpack2(a1);
        in_s[(2*ng)*160 + c]       = v0.x + feats[gn0 * DD + c];
        in_s[(2*ng)*160 + c + 1]   = v0.y + feats[gn0 * DD + c + 1];
        in_s[(2*ng+1)*160 + c]     = v1.x + feats[(gn0+1) * DD + c];
        in_s[(2*ng+1)*160 + c + 1] = v1.y + feats[(gn0+1) * DD + c + 1];
    }
    __syncthreads();

    for (int c = tid; c < DD; c += 256) {
        float s = 0.f;
        #pragma unroll
        for (int gg = 0; gg < 8; gg++) s += in_s[gg * 160 + c];
        g_part[(size_t)blockIdx.x * DD + c] = s;
    }
}

// ---------------- kernel 5: pool + head --------------------------------------
__global__ void head_kernel(const float* __restrict__ Wout,
                            const float* __restrict__ bout,
                            float* __restrict__ out) {
    __shared__ float red[256];
    int b = blockIdx.x, tid = threadIdx.x;
    const int blocksPerBatch = NN / 8;
    float v = 0.f;
    if (tid < DD) {
        float s = 0.f;
        const float* pp = g_part + ((size_t)b * blocksPerBatch) * DD + tid;
        for (int blk = 0; blk < blocksPerBatch; blk++) s += pp[(size_t)blk * DD];
        float emb = s * (1.f / (float)NN);
        v = emb * Wout[tid];
    }
    red[tid] = v;
    __syncthreads();
    for (int s2 = 128; s2 > 0; s2 >>= 1) {
        if (tid < s2) red[tid] += red[tid + s2];
        __syncthreads();
    }
    if (tid == 0) out[b] = red[0] + bout[0];
}

// ---------------- launch ----------------------------------------------------
extern "C" void kernel_launch(void* const* d_in, const int* in_sizes, int n_in,
                              void* d_out, int out_size) {
    const float* feats = (const float*)d_in[0];
    const float* coors = (const float*)d_in[1];
    const float* We1  = (const float*)d_in[3];
    const float* be1  = (const float*)d_in[4];
    const float* We2  = (const float*)d_in[5];
    const float* be2  = (const float*)d_in[6];
    const float* lng  = (const float*)d_in[11];
    const float* lnb  = (const float*)d_in[12];
    const float* Wn1  = (const float*)d_in[13];
    const float* bn1  = (const float*)d_in[14];
    const float* Wn2  = (const float*)d_in[15];
    const float* bn2  = (const float*)d_in[16];
    const float* Wout = (const float*)d_in[17];
    const float* bout = (const float*)d_in[18];
    float* out = (float*)d_out;

    knn_kernel<<<BB * NN, 256>>>(coors);
    dim3 pg(20, 256);
    prep_kernel<<<pg, 256>>>(feats, We1, be1);
    edge_kernel<<<(BB * NN) / GN, ETH>>>(We1, We2, be2);
    node_kernel<<<(BB * NN) / 8, 256>>>(feats, lng, lnb, Wn1, bn1, Wn2, bn2);
    head_kernel<<<BB, 256>>>(Wout, bout, out);
}